// round 15
// baseline (speedup 1.0000x reference)
#include <cuda_runtime.h>
#include <cuda_fp16.h>
#include <cstdint>

#define NB 8
#define NSQ 128
#define NH 512
#define NSTEPS 8
#define ROWS (NB*NSQ)   /* 1024 */
#define NW 2048

// fp16 GEMM: CTA 128x128, 16 warps (4x4) of 32x32, K-chunk 64 halves
#define KC 64
#define NCH (NH/KC)             /* 8 */
#define A_SLH (128*KC)          /* halves per chunk buffer (16 KB) */
#define SMEM_DYN (4*A_SLH*2)    /* 2 A + 2 B chunks = 64 KB */

// ---------------------------------------------------------------------------
// Scratch (device globals)
// ---------------------------------------------------------------------------
__device__ __align__(16) __half g_x[ROWS*NH];
__device__ __align__(16) __half g_ipre[ROWS*NH];    // fp16 pre-activation
__device__ __align__(16) float g_o[ROWS*NH];
__device__ __align__(16) float g_u[ROWS*NH];
__device__ __align__(16) __half g_fx[ROWS*NH];      // fp16 pre-activation
__device__ __align__(16) __half g_Wt_pre[NW*NH];
__device__ __align__(16) __half g_Wt_step[NW*NH];
__device__ __align__(16) float g_bstep[NW];
__device__ __align__(16) __half g_G[ROWS*NW];       // fp16 pre-activation
__device__ __align__(16) float g_h[ROWS*NH];
__device__ __align__(16) __half g_hr[ROWS*NH];
__device__ __align__(16) float g_c[2][ROWS*NH];
__device__ int g_listIU[NSTEPS*NB*NSQ*256];
__device__ int g_cntIU[NSTEPS*NB*NSQ];
__device__ int g_cntR[NSTEPS*NB*NSQ];
__device__ int g_listD[NSTEPS*NB*NSQ*128];
__device__ int g_cntD[NSTEPS*NB*NSQ];
__device__ int g_maskv[NSTEPS*ROWS];
__device__ int g_dest[NSTEPS*ROWS];
__device__ int g_nmask[NSTEPS];
__device__ int g_arr[NSTEPS*NB];                    // per-(step,batch) barrier

// ---------------------------------------------------------------------------
// Helpers
// ---------------------------------------------------------------------------
__device__ __forceinline__ uint32_t smem_u32(const void* p) {
    uint32_t a;
    asm("{ .reg .u64 t; cvta.to.shared.u64 t, %1; cvt.u32.u64 %0, t; }"
        : "=r"(a) : "l"(p));
    return a;
}
__device__ __forceinline__ void cp16(uint32_t s, const void* g) {
    asm volatile("cp.async.cg.shared.global [%0], [%1], 16;"
                 :: "r"(s), "l"(g) : "memory");
}
__device__ __forceinline__ void cp_commit() {
    asm volatile("cp.async.commit_group;" ::: "memory");
}
template <int N>
__device__ __forceinline__ void cp_wait() {
    asm volatile("cp.async.wait_group %0;" :: "n"(N) : "memory");
}
__device__ __forceinline__ void ldsm4(uint32_t& r0, uint32_t& r1,
                                      uint32_t& r2, uint32_t& r3,
                                      uint32_t addr) {
    asm volatile("ldmatrix.sync.aligned.m8n8.x4.shared.b16 {%0,%1,%2,%3}, [%4];"
        : "=r"(r0), "=r"(r1), "=r"(r2), "=r"(r3) : "r"(addr));
}
__device__ __forceinline__ void mma16816(float* d, const uint32_t* a,
                                         uint32_t b0, uint32_t b1) {
    asm("mma.sync.aligned.m16n8k16.row.col.f32.f16.f16.f32 "
        "{%0,%1,%2,%3}, {%4,%5,%6,%7}, {%8,%9}, {%0,%1,%2,%3};"
        : "+f"(d[0]), "+f"(d[1]), "+f"(d[2]), "+f"(d[3])
        : "r"(a[0]), "r"(a[1]), "r"(a[2]), "r"(a[3]), "r"(b0), "r"(b1));
}
__device__ __forceinline__ float sigf(float x) {
    return 1.0f / (1.0f + __expf(-x));
}
__device__ __forceinline__ float4 ldh4(const __half* p) {
    uint2 v = *(const uint2*)p;
    float2 f0 = __half22float2(*(__half2*)&v.x);
    float2 f1 = __half22float2(*(__half2*)&v.y);
    return make_float4(f0.x, f0.y, f1.x, f1.y);
}

// ---------------------------------------------------------------------------
// Per-row phase (identical math to R14 phase_k)
// ---------------------------------------------------------------------------
__device__ void phase_row(int r, int t, int step, int step0,
                          const float* __restrict__ c_cur,
                          float* __restrict__ c_nxt,
                          float* __restrict__ out) {
    const int b = r >> 7, n = r & 127;
    const int browbase = b * NSQ;
    const int sb = step * 8 + b;

    float4 acc = make_float4(0.f, 0.f, 0.f, 0.f);
    const int cnt = g_cntIU[sb * 128 + n];
    if (step0) {
        int nr = g_cntR[sb * 128 + n];
        int nl = cnt - nr;
        float4 bAr = ((const float4*)g_bstep)[t];
        float4 bAl = ((const float4*)g_bstep)[128 + t];
        float fr = (float)nr, fl = (float)nl;
        acc.x = fr * bAr.x + fl * bAl.x;
        acc.y = fr * bAr.y + fl * bAl.y;
        acc.z = fr * bAr.z + fl * bAl.z;
        acc.w = fr * bAr.w + fl * bAl.w;
    } else {
        const int* lst = g_listIU + ((size_t)sb * 128 + n) * 256;
        for (int k = 0; k < cnt; k++) {
            int e = lst[k];
            int sp = e & 255, seg = e >> 8;
            float4 v = ldh4(g_G + (size_t)(browbase + sp) * NW +
                            seg * 512 + t * 4);
            acc.x += v.x; acc.y += v.y; acc.z += v.z; acc.w += v.w;
        }
    }

    float4 ip = ldh4(g_ipre + (size_t)r * NH + t * 4);
    float4 uv = ((const float4*)g_u)[(size_t)r * 128 + t];
    float4 cf;
    cf.x = sigf(ip.x + acc.x) * uv.x;
    cf.y = sigf(ip.y + acc.y) * uv.y;
    cf.z = sigf(ip.z + acc.z) * uv.z;
    cf.w = sigf(ip.w + acc.w) * uv.w;

    if (!step0) {
        const int cd = g_cntD[sb * 128 + n];
        if (cd) {
            const int* ld = g_listD + ((size_t)sb * 128 + n) * 128;
            float4 fx4 = ldh4(g_fx + (size_t)r * NH + t * 4);
            for (int k = 0; k < cd; k++) {
                int e = ld[k];
                int sp = e & 255;
                int rr = (e >> 16) & 255, ll = (e >> 24) & 255;
                float4 fr4 = ldh4(g_G + (size_t)(browbase + rr) * NW +
                                  1024 + t * 4);
                float4 fl4 = ldh4(g_G + (size_t)(browbase + ll) * NW +
                                  1536 + t * 4);
                float4 cv  = ((const float4*)c_cur)[(size_t)(browbase + sp) * 128 + t];
                cf.x += sigf(fx4.x + fr4.x + fl4.x) * cv.x;
                cf.y += sigf(fx4.y + fr4.y + fl4.y) * cv.y;
                cf.z += sigf(fx4.z + fr4.z + fl4.z) * cv.z;
                cf.w += sigf(fx4.w + fr4.w + fl4.w) * cv.w;
            }
        }
    }

    float4 ov = ((const float4*)g_o)[(size_t)r * 128 + t];
    float4 hf;
    hf.x = ov.x * tanhf(cf.x);
    hf.y = ov.y * tanhf(cf.y);
    hf.z = ov.z * tanhf(cf.z);
    hf.w = ov.w * tanhf(cf.w);

    const int nm = g_nmask[step];
    if (r < nm) {
        const int q = g_dest[step * ROWS + r];
        if (out) {
            ((float4*)out)[(size_t)q * 128 + t] = hf;
        } else {
            ((float4*)g_h)[(size_t)q * 128 + t] = hf;
            ((float4*)c_nxt)[(size_t)q * 128 + t] = cf;
            __half2* hrw = (__half2*)(g_hr + (size_t)q * NH + t * 4);
            hrw[0] = __floats2half2_rn(hf.x, hf.y);
            hrw[1] = __floats2half2_rn(hf.z, hf.w);
        }
    }
    if (!g_maskv[step * ROWS + r]) {
        if (out) {
            ((float4*)out)[(size_t)r * 128 + t] =
                ((const float4*)g_h)[(size_t)r * 128 + t];
        } else {
            ((float4*)c_nxt)[(size_t)r * 128 + t] =
                ((const float4*)c_cur)[(size_t)r * 128 + t];
        }
    }
}

// ---------------------------------------------------------------------------
// Fused fp16 GEMM + per-batch barrier + phase.
// grid (16, 8): 128 CTAs, 1/SM, all resident. mode 1 = act-split preGEMM.
// ---------------------------------------------------------------------------
__global__ __launch_bounds__(512, 1)
void gemm_phase(const __half* __restrict__ A, const __half* __restrict__ Bt,
                const float* __restrict__ bias, int mode,
                int step, int step0, int cur, float* __restrict__ out) {
    extern __shared__ __half smh[];
    const uint32_t smbase = smem_u32(smh);

    const int tid  = threadIdx.x;
    const int wid  = tid >> 5, lane = tid & 31;
    const int lq   = lane >> 2, cq = lane & 3;
    const int mw   = wid >> 2, nw = wid & 3;
    const int bm   = blockIdx.y * 128, bn = blockIdx.x * 128;

    const int rowin = lane & 7;
    const int jA    = lane >> 3;
    const int jAlo  = (jA & 1) << 3;
    const int jAhi  = jA >> 1;

    int abyte[2], asw[2];
#pragma unroll
    for (int mt = 0; mt < 2; mt++) {
        int r = mw * 32 + mt * 16 + jAlo + rowin;
        abyte[mt] = r * 128; asw[mt] = r & 7;
    }
    int bbyte[4], bsw[4];
#pragma unroll
    for (int nt = 0; nt < 4; nt++) {
        int r = nw * 32 + nt * 8 + rowin;
        bbyte[nt] = r * 128; bsw[nt] = r & 7;
    }

    auto issue = [&](int s, int buf) {
        __half* da = smh + buf * A_SLH;
        __half* db = smh + (2 + buf) * A_SLH;
#pragma unroll
        for (int i = 0; i < 2; i++) {
            int idx = tid + (i << 9);
            int row = idx >> 3, c4 = idx & 7;
            cp16(smem_u32(da + row * KC + ((c4 ^ (row & 7)) << 3)),
                 A + (size_t)(bm + row) * NH + s * KC + (c4 << 3));
            cp16(smem_u32(db + row * KC + ((c4 ^ (row & 7)) << 3)),
                 Bt + (size_t)(bn + row) * NH + s * KC + (c4 << 3));
        }
        cp_commit();
    };

    float acc[2][4][4];
#pragma unroll
    for (int mt = 0; mt < 2; mt++)
#pragma unroll
        for (int nt = 0; nt < 4; nt++)
#pragma unroll
            for (int q = 0; q < 4; q++) acc[mt][nt][q] = 0.f;

    issue(0, 0);

    for (int s = 0; s < NCH; s++) {
        const int buf = s & 1;
        cp_wait<0>();
        __syncthreads();
        if (s + 1 < NCH) issue(s + 1, buf ^ 1);

        const uint32_t aB = smbase + (uint32_t)buf * (A_SLH * 2);
        const uint32_t bB = smbase + (uint32_t)(2 + buf) * (A_SLH * 2);
#pragma unroll
        for (int p = 0; p < 2; p++) {
            uint32_t br[4][4];
#pragma unroll
            for (int nt = 0; nt < 4; nt++)
                ldsm4(br[nt][0], br[nt][1], br[nt][2], br[nt][3],
                      bB + bbyte[nt] + ((((p << 2) + jA) ^ bsw[nt]) << 4));
            uint32_t ar[2][2][4];
#pragma unroll
            for (int kkl = 0; kkl < 2; kkl++)
#pragma unroll
                for (int mt = 0; mt < 2; mt++)
                    ldsm4(ar[kkl][mt][0], ar[kkl][mt][1],
                          ar[kkl][mt][2], ar[kkl][mt][3],
                          aB + abyte[mt] +
                          ((((p << 2) + (kkl << 1) + jAhi) ^ asw[mt]) << 4));
#pragma unroll
            for (int kkl = 0; kkl < 2; kkl++)
#pragma unroll
                for (int nt = 0; nt < 4; nt++)
#pragma unroll
                    for (int mt = 0; mt < 2; mt++)
                        mma16816(acc[mt][nt], ar[kkl][mt],
                                 br[nt][kkl << 1], br[nt][(kkl << 1) + 1]);
        }
    }

    if (mode == 0) {
#pragma unroll
        for (int mt = 0; mt < 2; mt++) {
            int row0 = bm + mw * 32 + mt * 16 + lq;
#pragma unroll
            for (int nt = 0; nt < 4; nt++) {
                int col = bn + nw * 32 + nt * 8 + (cq << 1);
                float bx = bias[col], by = bias[col + 1];
                *(__half2*)(g_G + (size_t)row0 * NW + col) =
                    __floats2half2_rn(acc[mt][nt][0] + bx, acc[mt][nt][1] + by);
                *(__half2*)(g_G + (size_t)(row0 + 8) * NW + col) =
                    __floats2half2_rn(acc[mt][nt][2] + bx, acc[mt][nt][3] + by);
            }
        }
    } else {
        const int seg = bn >> 9;
#pragma unroll
        for (int mt = 0; mt < 2; mt++) {
            int row0 = bm + mw * 32 + mt * 16 + lq;
#pragma unroll
            for (int nt = 0; nt < 4; nt++) {
                int lcol = (bn & 511) + nw * 32 + nt * 8 + (cq << 1);
                float v[4] = { acc[mt][nt][0], acc[mt][nt][1],
                               acc[mt][nt][2], acc[mt][nt][3] };
                if (seg == 0) {
                    *(__half2*)(g_ipre + (size_t)row0 * NH + lcol) =
                        __floats2half2_rn(v[0], v[1]);
                    *(__half2*)(g_ipre + (size_t)(row0 + 8) * NH + lcol) =
                        __floats2half2_rn(v[2], v[3]);
                } else if (seg == 1) {
                    *(float2*)(g_o + (size_t)row0 * NH + lcol) =
                        make_float2(sigf(v[0]), sigf(v[1]));
                    *(float2*)(g_o + (size_t)(row0 + 8) * NH + lcol) =
                        make_float2(sigf(v[2]), sigf(v[3]));
                } else if (seg == 2) {
                    *(float2*)(g_u + (size_t)row0 * NH + lcol) =
                        make_float2(tanhf(v[0]), tanhf(v[1]));
                    *(float2*)(g_u + (size_t)(row0 + 8) * NH + lcol) =
                        make_float2(tanhf(v[2]), tanhf(v[3]));
                } else {
                    *(__half2*)(g_fx + (size_t)row0 * NH + lcol) =
                        __floats2half2_rn(v[0], v[1]);
                    *(__half2*)(g_fx + (size_t)(row0 + 8) * NH + lcol) =
                        __floats2half2_rn(v[2], v[3]);
                }
            }
        }
    }

    // ---- per-batch-row barrier (16 CTAs share blockIdx.y) ----
    __threadfence();                          // release: tile stores visible
    __syncthreads();
    int* ctr = &g_arr[step * NB + blockIdx.y];
    if (tid == 0) {
        atomicAdd(ctr, 1);
        while (atomicAdd(ctr, 0) < 16) { }
    }
    __syncthreads();
    __threadfence();                          // acquire

    // ---- phase: this CTA handles 8 rows of its batch ----
    const float* c_cur = g_c[cur];
    float* c_nxt = g_c[cur ^ 1];
    const int t = tid & 127;
#pragma unroll
    for (int jj = 0; jj < 2; jj++) {
        int n = (blockIdx.x << 3) + (jj << 2) + (tid >> 7);
        int r = (blockIdx.y << 7) + n;
        phase_row(r, t, step, step0, c_cur, c_nxt, out);
    }
}

// ---------------------------------------------------------------------------
// Single merged prep kernel (R14 + barrier-counter zeroing)
// ---------------------------------------------------------------------------
__global__ __launch_bounds__(256)
void prep_k(const int* __restrict__ ids, const float* __restrict__ emb,
            const int* __restrict__ tree,
            const float* __restrict__ Wioux, const float* __restrict__ Wfx,
            const float* __restrict__ Wr, const float* __restrict__ Wl,
            const float* __restrict__ f0, const float* __restrict__ f1,
            const float* __restrict__ f2, const float* __restrict__ f3,
            const float* __restrict__ br, const float* __restrict__ bl,
            const float* __restrict__ bf0, const float* __restrict__ bf1,
            const float* __restrict__ bf2, const float* __restrict__ bf3) {
    const int blk = blockIdx.x;
    const int t = threadIdx.x;

    if (blk < 2048) {                       // ---- transposes ----
        __shared__ float tile[32][33];
        int y = blk >> 4;
        const float *s1, *s2 = nullptr;
        __half* dst; int n_off, ld1, ny;
        if (y < 48)       { dst = g_Wt_pre;  n_off = 0;    s1 = Wioux; ld1 = 1536; ny = y; }
        else if (y < 64)  { dst = g_Wt_pre;  n_off = 1536; s1 = Wfx;   ld1 = 512;  ny = y - 48; }
        else if (y < 80)  { dst = g_Wt_step; n_off = 0;    s1 = Wr;    ld1 = 1536; ny = y - 64; }
        else if (y < 96)  { dst = g_Wt_step; n_off = 512;  s1 = Wl;    ld1 = 1536; ny = y - 80; }
        else if (y < 112) { dst = g_Wt_step; n_off = 1024; s1 = f0; s2 = f1; ld1 = 512; ny = y - 96; }
        else              { dst = g_Wt_step; n_off = 1536; s1 = f2; s2 = f3; ld1 = 512; ny = y - 112; }

        int k0 = (blk & 15) * 32, n0 = ny * 32;
        int tx = t & 31, ty = t >> 5;
        for (int i = ty; i < 32; i += 8) {
            float v = s1[(size_t)(k0 + i) * ld1 + n0 + tx];
            if (s2) v += s2[(size_t)(k0 + i) * NH + n0 + tx];
            tile[i][tx] = v;
        }
        __syncthreads();
        for (int i = ty; i < 32; i += 8) {
            dst[(size_t)(n_off + n0 + i) * NH + k0 + tx] =
                __float2half(tile[tx][i]);
        }
    } else if (blk < 2560) {                // ---- init ----
        int row = (blk - 2048) * 2 + (t >> 7);
        int tt = t & 127;
        int tok = ids[row];
        float4 v = ((const float4*)emb)[(size_t)tok * 128 + tt];
        __half2* xw = (__half2*)(g_x + (size_t)row * NH + tt * 4);
        xw[0] = __floats2half2_rn(v.x, v.y);
        xw[1] = __floats2half2_rn(v.z, v.w);
        float4 z = make_float4(0.f, 0.f, 0.f, 0.f);
        ((float4*)g_h)[(size_t)row * 128 + tt]      = z;
        ((float4*)(g_c[0]))[(size_t)row * 128 + tt] = z;
        __half2 zh = __floats2half2_rn(0.f, 0.f);
        __half2* hrw = (__half2*)(g_hr + (size_t)row * NH + tt * 4);
        hrw[0] = zh; hrw[1] = zh;
        if (row < 4) {
            int j = tt * 4;
            const float* s1 = (row == 0) ? br : (row == 1) ? bl
                            : (row == 2) ? bf0 : bf2;
            const float* s2 = (row == 2) ? bf1 : (row == 3) ? bf3 : nullptr;
            float4 bv = *(const float4*)(s1 + j);
            if (s2) {
                float4 b2v = *(const float4*)(s2 + j);
                bv.x += b2v.x; bv.y += b2v.y; bv.z += b2v.z; bv.w += b2v.w;
            }
            *(float4*)(g_bstep + row * 512 + j) = bv;
        }
    } else if (blk < 2624) {                // ---- lists ----
        __shared__ int s_id[NSQ], s_ir[NSQ], s_il[NSQ];
        int sb = blk - 2560;
        int s = sb >> 3, b = sb & 7;
        int base = (b * NSTEPS + s) * 3;
        if (t < 128) {
            s_id[t] = tree[(base + 0) * NSQ + t];
            s_ir[t] = tree[(base + 1) * NSQ + t];
            s_il[t] = tree[(base + 2) * NSQ + t];
        }
        __syncthreads();
        if (t < 128) {
            int n = t;
            int* lIU = g_listIU + ((size_t)sb * 128 + n) * 256;
            int c = 0;
            for (int sp = 0; sp < NSQ; sp++) if (s_ir[sp] == n) lIU[c++] = sp;
            int cr = c;
            for (int sp = 0; sp < NSQ; sp++) if (s_il[sp] == n) lIU[c++] = sp | 256;
            g_cntIU[sb * 128 + n] = c;
            g_cntR[sb * 128 + n] = cr;
            int* lD = g_listD + ((size_t)sb * 128 + n) * 128;
            int cd = 0;
            for (int sp = 0; sp < NSQ; sp++)
                if (s_id[sp] == n)
                    lD[cd++] = sp | (s_ir[sp] << 16) | (s_il[sp] << 24);
            g_cntD[sb * 128 + n] = cd;
        }
    } else {                                // ---- ranks + barrier zero ----
        __shared__ int wsum[8];
        int s = blk - 2624;
        int lane = t & 31, w = t >> 5;
        if (t < NB) g_arr[s * NB + t] = 0;
        int m[4], loc[4];
        int sum = 0;
#pragma unroll
        for (int q = 0; q < 4; q++) {
            int p = t * 4 + q;
            int b = p >> 7, ss = p & 127;
            int idxd = tree[((b * NSTEPS + s) * 3) * NSQ + ss];
            m[q] = (idxd != 0) ? 1 : 0;
            g_maskv[s * ROWS + p] = m[q];
            loc[q] = sum;
            sum += m[q];
        }
        int e = sum;
#pragma unroll
        for (int off = 1; off < 32; off <<= 1) {
            int o = __shfl_up_sync(0xFFFFFFFFu, e, off);
            if (lane >= off) e += o;
        }
        if (lane == 31) wsum[w] = e;
        __syncthreads();
        if (t == 0) {
            int a = 0;
#pragma unroll
            for (int i = 0; i < 8; i++) { int v = wsum[i]; wsum[i] = a; a += v; }
            g_nmask[s] = a;
        }
        __syncthreads();
        int pre = wsum[w] + e - sum;
#pragma unroll
        for (int q = 0; q < 4; q++)
            if (m[q]) g_dest[s * ROWS + pre + loc[q]] = t * 4 + q;
    }
}

// ---------------------------------------------------------------------------
// Launch: prep + 8 fused GEMM+phase kernels (9 graph nodes)
// ---------------------------------------------------------------------------
extern "C" void kernel_launch(void* const* d_in, const int* in_sizes, int n_in,
                              void* d_out, int out_size) {
    const int*   ids      = (const int*)d_in[0];
    const int*   tree     = (const int*)d_in[1];
    const float* emb      = (const float*)d_in[2];
    const float* W_ioux   = (const float*)d_in[3];
    const float* W_iouh_r = (const float*)d_in[4];
    const float* b_iouh_r = (const float*)d_in[5];
    const float* W_iouh_l = (const float*)d_in[6];
    const float* b_iouh_l = (const float*)d_in[7];
    const float* W_fx     = (const float*)d_in[8];
    const float* W_fh0    = (const float*)d_in[9];
    const float* b_fh0    = (const float*)d_in[10];
    const float* W_fh1    = (const float*)d_in[11];
    const float* b_fh1    = (const float*)d_in[12];
    const float* W_fh2    = (const float*)d_in[13];
    const float* b_fh2    = (const float*)d_in[14];
    const float* W_fh3    = (const float*)d_in[15];
    const float* b_fh3    = (const float*)d_in[16];

    cudaFuncSetAttribute(gemm_phase,
                         cudaFuncAttributeMaxDynamicSharedMemorySize, SMEM_DYN);

    __half *pX, *pWtPre, *pWtStep, *pHr;
    float *pB;
    cudaGetSymbolAddress((void**)&pX,      g_x);
    cudaGetSymbolAddress((void**)&pWtPre,  g_Wt_pre);
    cudaGetSymbolAddress((void**)&pWtStep, g_Wt_step);
    cudaGetSymbolAddress((void**)&pB,      g_bstep);
    cudaGetSymbolAddress((void**)&pHr,     g_hr);

    prep_k<<<2632, 256>>>(ids, emb, tree, W_ioux, W_fx,
                          W_iouh_r, W_iouh_l, W_fh0, W_fh1, W_fh2, W_fh3,
                          b_iouh_r, b_iouh_l, b_fh0, b_fh1, b_fh2, b_fh3);

    // step 0: preGEMM (act-split) fused with phase0 (h=0 -> bias counts; c=0)
    gemm_phase<<<dim3(16, 8), 512, SMEM_DYN>>>(pX, pWtPre, nullptr, 1,
                                               0, 1, 0, nullptr);

    for (int s = 1; s < NSTEPS; s++) {
        gemm_phase<<<dim3(16, 8), 512, SMEM_DYN>>>(
            pHr, pWtStep, pB, 0, s, 0, s & 1,
            (s == NSTEPS - 1) ? (float*)d_out : nullptr);
    }
}

// round 16
// speedup vs baseline: 1.1657x; 1.1657x over previous
#include <cuda_runtime.h>
#include <cuda_fp16.h>
#include <cstdint>

#define NB 8
#define NSQ 128
#define NH 512
#define NSTEPS 8
#define ROWS (NB*NSQ)   /* 1024 */
#define NW 2048

// fp16 GEMM: CTA 128x128, 16 warps (4x4) of 32x32, K-chunk 64 halves
#define KC 64
#define NCH (NH/KC)             /* 8 */
#define A_SLH (128*KC)          /* halves per chunk buffer (16 KB) */
#define SMEM_DYN (4*A_SLH*2)    /* 2 A + 2 B chunks = 64 KB */

// ---------------------------------------------------------------------------
// Scratch (device globals)
// ---------------------------------------------------------------------------
__device__ __align__(16) __half g_x[ROWS*NH];
__device__ __align__(16) __half g_ipre[ROWS*NH];    // fp16 pre-activation
__device__ __align__(16) float g_o[ROWS*NH];        // post-activation: fp32
__device__ __align__(16) float g_u[ROWS*NH];        // post-activation: fp32
__device__ __align__(16) __half g_fx[ROWS*NH];      // fp16 pre-activation
__device__ __align__(16) __half g_Wt_pre[NW*NH];
__device__ __align__(16) __half g_Wt_step[NW*NH];
__device__ __align__(16) float g_bstep[NW];
__device__ __align__(16) __half g_G[ROWS*NW];       // fp16 pre-activation
__device__ __align__(16) float g_h[ROWS*NH];
__device__ __align__(16) __half g_hr[ROWS*NH];
__device__ __align__(16) float g_c[2][ROWS*NH];
__device__ int g_listIU[NSTEPS*NB*NSQ*256];
__device__ int g_cntIU[NSTEPS*NB*NSQ];
__device__ int g_cntR[NSTEPS*NB*NSQ];
__device__ int g_listD[NSTEPS*NB*NSQ*128];
__device__ int g_cntD[NSTEPS*NB*NSQ];
__device__ int g_maskv[NSTEPS*ROWS];
__device__ int g_dest[NSTEPS*ROWS];
__device__ int g_nmask[NSTEPS];

// ---------------------------------------------------------------------------
// Helpers
// ---------------------------------------------------------------------------
__device__ __forceinline__ uint32_t smem_u32(const void* p) {
    uint32_t a;
    asm("{ .reg .u64 t; cvta.to.shared.u64 t, %1; cvt.u32.u64 %0, t; }"
        : "=r"(a) : "l"(p));
    return a;
}
__device__ __forceinline__ void cp16(uint32_t s, const void* g) {
    asm volatile("cp.async.cg.shared.global [%0], [%1], 16;"
                 :: "r"(s), "l"(g) : "memory");
}
__device__ __forceinline__ void cp_commit() {
    asm volatile("cp.async.commit_group;" ::: "memory");
}
template <int N>
__device__ __forceinline__ void cp_wait() {
    asm volatile("cp.async.wait_group %0;" :: "n"(N) : "memory");
}
__device__ __forceinline__ void ldsm4(uint32_t& r0, uint32_t& r1,
                                      uint32_t& r2, uint32_t& r3,
                                      uint32_t addr) {
    asm volatile("ldmatrix.sync.aligned.m8n8.x4.shared.b16 {%0,%1,%2,%3}, [%4];"
        : "=r"(r0), "=r"(r1), "=r"(r2), "=r"(r3) : "r"(addr));
}
__device__ __forceinline__ void mma16816(float* d, const uint32_t* a,
                                         uint32_t b0, uint32_t b1) {
    asm("mma.sync.aligned.m16n8k16.row.col.f32.f16.f16.f32 "
        "{%0,%1,%2,%3}, {%4,%5,%6,%7}, {%8,%9}, {%0,%1,%2,%3};"
        : "+f"(d[0]), "+f"(d[1]), "+f"(d[2]), "+f"(d[3])
        : "r"(a[0]), "r"(a[1]), "r"(a[2]), "r"(a[3]), "r"(b0), "r"(b1));
}
__device__ __forceinline__ float sigf(float x) {
    return 1.0f / (1.0f + __expf(-x));
}
// load 4 consecutive halves -> float4
__device__ __forceinline__ float4 ldh4(const __half* p) {
    uint2 v = *(const uint2*)p;
    float2 f0 = __half22float2(*(__half2*)&v.x);
    float2 f1 = __half22float2(*(__half2*)&v.y);
    return make_float4(f0.x, f0.y, f1.x, f1.y);
}

// ---------------------------------------------------------------------------
// fp16 GEMM: C[1024,2048] = A[1024,512] @ Bt^T (+bias), f32 accum.
// mode 0: step GEMM -> g_G (fp16); mode 1: act-split -> ipre16/o/u/fx16
// ---------------------------------------------------------------------------
__global__ __launch_bounds__(512, 1)
void gemm_mma(const __half* __restrict__ A, const __half* __restrict__ Bt,
              const float* __restrict__ bias, int mode) {
    extern __shared__ __half smh[];
    const uint32_t smbase = smem_u32(smh);

    const int tid  = threadIdx.x;
    const int wid  = tid >> 5, lane = tid & 31;
    const int lq   = lane >> 2, cq = lane & 3;
    const int mw   = wid >> 2, nw = wid & 3;          // 4x4 warp grid
    const int bm   = blockIdx.y * 128, bn = blockIdx.x * 128;

    const int rowin = lane & 7;
    const int jA    = lane >> 3;
    const int jAlo  = (jA & 1) << 3;
    const int jAhi  = jA >> 1;

    int abyte[2], asw[2];
#pragma unroll
    for (int mt = 0; mt < 2; mt++) {
        int r = mw * 32 + mt * 16 + jAlo + rowin;
        abyte[mt] = r * 128; asw[mt] = r & 7;
    }
    int bbyte[4], bsw[4];
#pragma unroll
    for (int nt = 0; nt < 4; nt++) {
        int r = nw * 32 + nt * 8 + rowin;
        bbyte[nt] = r * 128; bsw[nt] = r & 7;
    }

    auto issue = [&](int s, int buf) {
        __half* da = smh + buf * A_SLH;
        __half* db = smh + (2 + buf) * A_SLH;
#pragma unroll
        for (int i = 0; i < 2; i++) {
            int idx = tid + (i << 9);
            int row = idx >> 3, c4 = idx & 7;
            cp16(smem_u32(da + row * KC + ((c4 ^ (row & 7)) << 3)),
                 A + (size_t)(bm + row) * NH + s * KC + (c4 << 3));
            cp16(smem_u32(db + row * KC + ((c4 ^ (row & 7)) << 3)),
                 Bt + (size_t)(bn + row) * NH + s * KC + (c4 << 3));
        }
        cp_commit();
    };

    float acc[2][4][4];
#pragma unroll
    for (int mt = 0; mt < 2; mt++)
#pragma unroll
        for (int nt = 0; nt < 4; nt++)
#pragma unroll
            for (int q = 0; q < 4; q++) acc[mt][nt][q] = 0.f;

    issue(0, 0);

    for (int s = 0; s < NCH; s++) {
        const int buf = s & 1;
        cp_wait<0>();
        __syncthreads();
        if (s + 1 < NCH) issue(s + 1, buf ^ 1);

        const uint32_t aB = smbase + (uint32_t)buf * (A_SLH * 2);
        const uint32_t bB = smbase + (uint32_t)(2 + buf) * (A_SLH * 2);
#pragma unroll
        for (int p = 0; p < 2; p++) {
            uint32_t br[4][4];
#pragma unroll
            for (int nt = 0; nt < 4; nt++)
                ldsm4(br[nt][0], br[nt][1], br[nt][2], br[nt][3],
                      bB + bbyte[nt] + ((((p << 2) + jA) ^ bsw[nt]) << 4));
            uint32_t ar[2][2][4];
#pragma unroll
            for (int kkl = 0; kkl < 2; kkl++)
#pragma unroll
                for (int mt = 0; mt < 2; mt++)
                    ldsm4(ar[kkl][mt][0], ar[kkl][mt][1],
                          ar[kkl][mt][2], ar[kkl][mt][3],
                          aB + abyte[mt] +
                          ((((p << 2) + (kkl << 1) + jAhi) ^ asw[mt]) << 4));
#pragma unroll
            for (int kkl = 0; kkl < 2; kkl++)
#pragma unroll
                for (int nt = 0; nt < 4; nt++)
#pragma unroll
                    for (int mt = 0; mt < 2; mt++)
                        mma16816(acc[mt][nt], ar[kkl][mt],
                                 br[nt][kkl << 1], br[nt][(kkl << 1) + 1]);
        }
    }

    if (mode == 0) {
#pragma unroll
        for (int mt = 0; mt < 2; mt++) {
            int row0 = bm + mw * 32 + mt * 16 + lq;
#pragma unroll
            for (int nt = 0; nt < 4; nt++) {
                int col = bn + nw * 32 + nt * 8 + (cq << 1);
                float bx = bias[col], by = bias[col + 1];
                *(__half2*)(g_G + (size_t)row0 * NW + col) =
                    __floats2half2_rn(acc[mt][nt][0] + bx, acc[mt][nt][1] + by);
                *(__half2*)(g_G + (size_t)(row0 + 8) * NW + col) =
                    __floats2half2_rn(acc[mt][nt][2] + bx, acc[mt][nt][3] + by);
            }
        }
    } else {
        const int seg = bn >> 9;
#pragma unroll
        for (int mt = 0; mt < 2; mt++) {
            int row0 = bm + mw * 32 + mt * 16 + lq;
#pragma unroll
            for (int nt = 0; nt < 4; nt++) {
                int lcol = (bn & 511) + nw * 32 + nt * 8 + (cq << 1);
                float v[4] = { acc[mt][nt][0], acc[mt][nt][1],
                               acc[mt][nt][2], acc[mt][nt][3] };
                if (seg == 0) {
                    *(__half2*)(g_ipre + (size_t)row0 * NH + lcol) =
                        __floats2half2_rn(v[0], v[1]);
                    *(__half2*)(g_ipre + (size_t)(row0 + 8) * NH + lcol) =
                        __floats2half2_rn(v[2], v[3]);
                } else if (seg == 1) {
                    *(float2*)(g_o + (size_t)row0 * NH + lcol) =
                        make_float2(sigf(v[0]), sigf(v[1]));
                    *(float2*)(g_o + (size_t)(row0 + 8) * NH + lcol) =
                        make_float2(sigf(v[2]), sigf(v[3]));
                } else if (seg == 2) {
                    *(float2*)(g_u + (size_t)row0 * NH + lcol) =
                        make_float2(tanhf(v[0]), tanhf(v[1]));
                    *(float2*)(g_u + (size_t)(row0 + 8) * NH + lcol) =
                        make_float2(tanhf(v[2]), tanhf(v[3]));
                } else {
                    *(__half2*)(g_fx + (size_t)row0 * NH + lcol) =
                        __floats2half2_rn(v[0], v[1]);
                    *(__half2*)(g_fx + (size_t)(row0 + 8) * NH + lcol) =
                        __floats2half2_rn(v[2], v[3]);
                }
            }
        }
    }
}

// ---------------------------------------------------------------------------
// Fully fused per-step phase (fp16 G/ipre/fx loads; fp32 compute)
// ---------------------------------------------------------------------------
__global__ __launch_bounds__(128)
void phase_k(int step, int step0, int cur, float* __restrict__ out) {
    const int r = blockIdx.x;
    const int t = threadIdx.x;
    const int b = r >> 7, n = r & 127;
    const int browbase = b * NSQ;
    const int sb = step * 8 + b;
    const float* c_cur = g_c[cur];
    float* c_nxt = g_c[cur ^ 1];

    float4 acc = make_float4(0.f, 0.f, 0.f, 0.f);
    const int cnt = g_cntIU[sb * 128 + n];
    if (step0) {
        int nr = g_cntR[sb * 128 + n];
        int nl = cnt - nr;
        float4 bAr = ((const float4*)g_bstep)[t];
        float4 bAl = ((const float4*)g_bstep)[128 + t];
        float fr = (float)nr, fl = (float)nl;
        acc.x = fr * bAr.x + fl * bAl.x;
        acc.y = fr * bAr.y + fl * bAl.y;
        acc.z = fr * bAr.z + fl * bAl.z;
        acc.w = fr * bAr.w + fl * bAl.w;
    } else {
        const int* lst = g_listIU + ((size_t)sb * 128 + n) * 256;
        for (int k = 0; k < cnt; k++) {
            int e = lst[k];
            int sp = e & 255, seg = e >> 8;
            float4 v = ldh4(g_G + (size_t)(browbase + sp) * NW +
                            seg * 512 + t * 4);
            acc.x += v.x; acc.y += v.y; acc.z += v.z; acc.w += v.w;
        }
    }

    float4 ip = ldh4(g_ipre + (size_t)r * NH + t * 4);
    float4 uv = ((const float4*)g_u)[(size_t)r * 128 + t];
    float4 cf;
    cf.x = sigf(ip.x + acc.x) * uv.x;
    cf.y = sigf(ip.y + acc.y) * uv.y;
    cf.z = sigf(ip.z + acc.z) * uv.z;
    cf.w = sigf(ip.w + acc.w) * uv.w;

    if (!step0) {
        const int cd = g_cntD[sb * 128 + n];
        if (cd) {
            const int* ld = g_listD + ((size_t)sb * 128 + n) * 128;
            float4 fx4 = ldh4(g_fx + (size_t)r * NH + t * 4);
            for (int k = 0; k < cd; k++) {
                int e = ld[k];
                int sp = e & 255;
                int rr = (e >> 16) & 255, ll = (e >> 24) & 255;
                float4 fr4 = ldh4(g_G + (size_t)(browbase + rr) * NW +
                                  1024 + t * 4);
                float4 fl4 = ldh4(g_G + (size_t)(browbase + ll) * NW +
                                  1536 + t * 4);
                float4 cv  = ((const float4*)c_cur)[(size_t)(browbase + sp) * 128 + t];
                cf.x += sigf(fx4.x + fr4.x + fl4.x) * cv.x;
                cf.y += sigf(fx4.y + fr4.y + fl4.y) * cv.y;
                cf.z += sigf(fx4.z + fr4.z + fl4.z) * cv.z;
                cf.w += sigf(fx4.w + fr4.w + fl4.w) * cv.w;
            }
        }
    }

    float4 ov = ((const float4*)g_o)[(size_t)r * 128 + t];
    float4 hf;
    hf.x = ov.x * tanhf(cf.x);
    hf.y = ov.y * tanhf(cf.y);
    hf.z = ov.z * tanhf(cf.z);
    hf.w = ov.w * tanhf(cf.w);

    const int nm = g_nmask[step];
    if (r < nm) {
        const int q = g_dest[step * ROWS + r];
        if (out) {
            ((float4*)out)[(size_t)q * 128 + t] = hf;
        } else {
            ((float4*)g_h)[(size_t)q * 128 + t] = hf;
            ((float4*)c_nxt)[(size_t)q * 128 + t] = cf;
            __half2* hrw = (__half2*)(g_hr + (size_t)q * NH + t * 4);
            hrw[0] = __floats2half2_rn(hf.x, hf.y);
            hrw[1] = __floats2half2_rn(hf.z, hf.w);
        }
    }
    if (!g_maskv[step * ROWS + r]) {
        if (out) {
            ((float4*)out)[(size_t)r * 128 + t] =
                ((const float4*)g_h)[(size_t)r * 128 + t];
        } else {
            ((float4*)c_nxt)[(size_t)r * 128 + t] =
                ((const float4*)c_cur)[(size_t)r * 128 + t];
        }
    }
}

// ---------------------------------------------------------------------------
// Single merged prep kernel
// ---------------------------------------------------------------------------
__global__ __launch_bounds__(256)
void prep_k(const int* __restrict__ ids, const float* __restrict__ emb,
            const int* __restrict__ tree,
            const float* __restrict__ Wioux, const float* __restrict__ Wfx,
            const float* __restrict__ Wr, const float* __restrict__ Wl,
            const float* __restrict__ f0, const float* __restrict__ f1,
            const float* __restrict__ f2, const float* __restrict__ f3,
            const float* __restrict__ br, const float* __restrict__ bl,
            const float* __restrict__ bf0, const float* __restrict__ bf1,
            const float* __restrict__ bf2, const float* __restrict__ bf3) {
    const int blk = blockIdx.x;
    const int t = threadIdx.x;

    if (blk < 2048) {                       // ---- transposes ----
        __shared__ float tile[32][33];
        int y = blk >> 4;
        const float *s1, *s2 = nullptr;
        __half* dst; int n_off, ld1, ny;
        if (y < 48)       { dst = g_Wt_pre;  n_off = 0;    s1 = Wioux; ld1 = 1536; ny = y; }
        else if (y < 64)  { dst = g_Wt_pre;  n_off = 1536; s1 = Wfx;   ld1 = 512;  ny = y - 48; }
        else if (y < 80)  { dst = g_Wt_step; n_off = 0;    s1 = Wr;    ld1 = 1536; ny = y - 64; }
        else if (y < 96)  { dst = g_Wt_step; n_off = 512;  s1 = Wl;    ld1 = 1536; ny = y - 80; }
        else if (y < 112) { dst = g_Wt_step; n_off = 1024; s1 = f0; s2 = f1; ld1 = 512; ny = y - 96; }
        else              { dst = g_Wt_step; n_off = 1536; s1 = f2; s2 = f3; ld1 = 512; ny = y - 112; }

        int k0 = (blk & 15) * 32, n0 = ny * 32;
        int tx = t & 31, ty = t >> 5;
        for (int i = ty; i < 32; i += 8) {
            float v = s1[(size_t)(k0 + i) * ld1 + n0 + tx];
            if (s2) v += s2[(size_t)(k0 + i) * NH + n0 + tx];
            tile[i][tx] = v;
        }
        __syncthreads();
        for (int i = ty; i < 32; i += 8) {
            dst[(size_t)(n_off + n0 + i) * NH + k0 + tx] =
                __float2half(tile[tx][i]);
        }
    } else if (blk < 2560) {                // ---- init ----
        int row = (blk - 2048) * 2 + (t >> 7);
        int tt = t & 127;
        int tok = ids[row];
        float4 v = ((const float4*)emb)[(size_t)tok * 128 + tt];
        __half2* xw = (__half2*)(g_x + (size_t)row * NH + tt * 4);
        xw[0] = __floats2half2_rn(v.x, v.y);
        xw[1] = __floats2half2_rn(v.z, v.w);
        float4 z = make_float4(0.f, 0.f, 0.f, 0.f);
        ((float4*)g_h)[(size_t)row * 128 + tt]      = z;
        ((float4*)(g_c[0]))[(size_t)row * 128 + tt] = z;
        __half2 zh = __floats2half2_rn(0.f, 0.f);
        __half2* hrw = (__half2*)(g_hr + (size_t)row * NH + tt * 4);
        hrw[0] = zh; hrw[1] = zh;
        if (row < 4) {
            int j = tt * 4;
            const float* s1 = (row == 0) ? br : (row == 1) ? bl
                            : (row == 2) ? bf0 : bf2;
            const float* s2 = (row == 2) ? bf1 : (row == 3) ? bf3 : nullptr;
            float4 bv = *(const float4*)(s1 + j);
            if (s2) {
                float4 b2v = *(const float4*)(s2 + j);
                bv.x += b2v.x; bv.y += b2v.y; bv.z += b2v.z; bv.w += b2v.w;
            }
            *(float4*)(g_bstep + row * 512 + j) = bv;
        }
    } else if (blk < 2624) {                // ---- lists ----
        __shared__ int s_id[NSQ], s_ir[NSQ], s_il[NSQ];
        int sb = blk - 2560;
        int s = sb >> 3, b = sb & 7;
        int base = (b * NSTEPS + s) * 3;
        if (t < 128) {
            s_id[t] = tree[(base + 0) * NSQ + t];
            s_ir[t] = tree[(base + 1) * NSQ + t];
            s_il[t] = tree[(base + 2) * NSQ + t];
        }
        __syncthreads();
        if (t < 128) {
            int n = t;
            int* lIU = g_listIU + ((size_t)sb * 128 + n) * 256;
            int c = 0;
            for (int sp = 0; sp < NSQ; sp++) if (s_ir[sp] == n) lIU[c++] = sp;
            int cr = c;
            for (int sp = 0; sp < NSQ; sp++) if (s_il[sp] == n) lIU[c++] = sp | 256;
            g_cntIU[sb * 128 + n] = c;
            g_cntR[sb * 128 + n] = cr;
            int* lD = g_listD + ((size_t)sb * 128 + n) * 128;
            int cd = 0;
            for (int sp = 0; sp < NSQ; sp++)
                if (s_id[sp] == n)
                    lD[cd++] = sp | (s_ir[sp] << 16) | (s_il[sp] << 24);
            g_cntD[sb * 128 + n] = cd;
        }
    } else {                                // ---- ranks ----
        __shared__ int wsum[8];
        int s = blk - 2624;
        int lane = t & 31, w = t >> 5;
        int m[4], loc[4];
        int sum = 0;
#pragma unroll
        for (int q = 0; q < 4; q++) {
            int p = t * 4 + q;
            int b = p >> 7, ss = p & 127;
            int idxd = tree[((b * NSTEPS + s) * 3) * NSQ + ss];
            m[q] = (idxd != 0) ? 1 : 0;
            g_maskv[s * ROWS + p] = m[q];
            loc[q] = sum;
            sum += m[q];
        }
        int e = sum;
#pragma unroll
        for (int off = 1; off < 32; off <<= 1) {
            int o = __shfl_up_sync(0xFFFFFFFFu, e, off);
            if (lane >= off) e += o;
        }
        if (lane == 31) wsum[w] = e;
        __syncthreads();
        if (t == 0) {
            int a = 0;
#pragma unroll
            for (int i = 0; i < 8; i++) { int v = wsum[i]; wsum[i] = a; a += v; }
            g_nmask[s] = a;
        }
        __syncthreads();
        int pre = wsum[w] + e - sum;
#pragma unroll
        for (int q = 0; q < 4; q++)
            if (m[q]) g_dest[s * ROWS + pre + loc[q]] = t * 4 + q;
    }
}

// ---------------------------------------------------------------------------
// Launch
// ---------------------------------------------------------------------------
extern "C" void kernel_launch(void* const* d_in, const int* in_sizes, int n_in,
                              void* d_out, int out_size) {
    const int*   ids      = (const int*)d_in[0];
    const int*   tree     = (const int*)d_in[1];
    const float* emb      = (const float*)d_in[2];
    const float* W_ioux   = (const float*)d_in[3];
    const float* W_iouh_r = (const float*)d_in[4];
    const float* b_iouh_r = (const float*)d_in[5];
    const float* W_iouh_l = (const float*)d_in[6];
    const float* b_iouh_l = (const float*)d_in[7];
    const float* W_fx     = (const float*)d_in[8];
    const float* W_fh0    = (const float*)d_in[9];
    const float* b_fh0    = (const float*)d_in[10];
    const float* W_fh1    = (const float*)d_in[11];
    const float* b_fh1    = (const float*)d_in[12];
    const float* W_fh2    = (const float*)d_in[13];
    const float* b_fh2    = (const float*)d_in[14];
    const float* W_fh3    = (const float*)d_in[15];
    const float* b_fh3    = (const float*)d_in[16];

    cudaFuncSetAttribute(gemm_mma, cudaFuncAttributeMaxDynamicSharedMemorySize,
                         SMEM_DYN);

    __half *pX, *pWtPre, *pWtStep, *pHr;
    float *pB;
    cudaGetSymbolAddress((void**)&pX,      g_x);
    cudaGetSymbolAddress((void**)&pWtPre,  g_Wt_pre);
    cudaGetSymbolAddress((void**)&pWtStep, g_Wt_step);
    cudaGetSymbolAddress((void**)&pB,      g_bstep);
    cudaGetSymbolAddress((void**)&pHr,     g_hr);

    prep_k<<<2632, 256>>>(ids, emb, tree, W_ioux, W_fx,
                          W_iouh_r, W_iouh_l, W_fh0, W_fh1, W_fh2, W_fh3,
                          b_iouh_r, b_iouh_l, b_fh0, b_fh1, b_fh2, b_fh3);

    // precompute GEMM with fused activation-split epilogue
    gemm_mma<<<dim3(NW / 128, ROWS / 128), 512, SMEM_DYN>>>(pX, pWtPre,
                                                            nullptr, 1);

    // step 0: h=0 (i-gate from bias counts), c=0 (no fc)
    phase_k<<<ROWS, 128>>>(0, 1, 0, nullptr);

    int cur = 1;
    for (int s = 1; s < NSTEPS; s++) {
        gemm_mma<<<dim3(NW / 128, ROWS / 128), 512, SMEM_DYN>>>(
            pHr, pWtStep, pB, 0);
        phase_k<<<ROWS, 128>>>(s, 0, cur,
                               (s == NSTEPS - 1) ? (float*)d_out : nullptr);
        cur ^= 1;
    }
}

// round 17
// speedup vs baseline: 1.1695x; 1.0033x over previous
#include <cuda_runtime.h>
#include <cuda_fp16.h>
#include <cstdint>

#define NB 8
#define NSQ 128
#define NH 512
#define NSTEPS 8
#define ROWS (NB*NSQ)   /* 1024 */
#define NW 2048

// fp16 GEMM: CTA 128x128, 16 warps (4x4) of 32x32, K-chunk 64 halves
#define KC 64
#define NCH (NH/KC)             /* 8 */
#define A_SLH (128*KC)          /* halves per chunk buffer (16 KB) */
#define SMEM_DYN (4*A_SLH*2)    /* 2 A + 2 B chunks = 64 KB */

// ---------------------------------------------------------------------------
// Scratch (device globals)
// ---------------------------------------------------------------------------
__device__ __align__(16) __half g_x[ROWS*NH];
__device__ __align__(16) __half g_ipre[ROWS*NH];    // fp16 pre-activation
__device__ __align__(16) float g_o[ROWS*NH];        // post-activation: fp32
__device__ __align__(16) float g_u[ROWS*NH];        // post-activation: fp32
__device__ __align__(16) __half g_fx[ROWS*NH];      // fp16 pre-activation
__device__ __align__(16) __half g_Wt_pre[NW*NH];
__device__ __align__(16) __half g_Wt_step[NW*NH];
__device__ __align__(16) float g_bstep[NW];
__device__ __align__(16) __half g_G[ROWS*NW];       // fp16 pre-activation
__device__ __align__(16) float g_h[ROWS*NH];
__device__ __align__(16) __half g_hr[ROWS*NH];
__device__ __align__(16) float g_c[2][ROWS*NH];
__device__ int g_listIU[NSTEPS*NB*NSQ*256];
__device__ int g_cntIU[NSTEPS*NB*NSQ];
__device__ int g_cntR[NSTEPS*NB*NSQ];
__device__ int g_listD[NSTEPS*NB*NSQ*128];
__device__ int g_cntD[NSTEPS*NB*NSQ];
__device__ int g_maskv[NSTEPS*ROWS];
__device__ int g_dest[NSTEPS*ROWS];
__device__ int g_nmask[NSTEPS];

// ---------------------------------------------------------------------------
// Helpers
// ---------------------------------------------------------------------------
__device__ __forceinline__ uint32_t smem_u32(const void* p) {
    uint32_t a;
    asm("{ .reg .u64 t; cvta.to.shared.u64 t, %1; cvt.u32.u64 %0, t; }"
        : "=r"(a) : "l"(p));
    return a;
}
__device__ __forceinline__ void cp16(uint32_t s, const void* g) {
    asm volatile("cp.async.cg.shared.global [%0], [%1], 16;"
                 :: "r"(s), "l"(g) : "memory");
}
__device__ __forceinline__ void cp_commit() {
    asm volatile("cp.async.commit_group;" ::: "memory");
}
template <int N>
__device__ __forceinline__ void cp_wait() {
    asm volatile("cp.async.wait_group %0;" :: "n"(N) : "memory");
}
__device__ __forceinline__ void ldsm4(uint32_t& r0, uint32_t& r1,
                                      uint32_t& r2, uint32_t& r3,
                                      uint32_t addr) {
    asm volatile("ldmatrix.sync.aligned.m8n8.x4.shared.b16 {%0,%1,%2,%3}, [%4];"
        : "=r"(r0), "=r"(r1), "=r"(r2), "=r"(r3) : "r"(addr));
}
__device__ __forceinline__ void mma16816(float* d, const uint32_t* a,
                                         uint32_t b0, uint32_t b1) {
    asm("mma.sync.aligned.m16n8k16.row.col.f32.f16.f16.f32 "
        "{%0,%1,%2,%3}, {%4,%5,%6,%7}, {%8,%9}, {%0,%1,%2,%3};"
        : "+f"(d[0]), "+f"(d[1]), "+f"(d[2]), "+f"(d[3])
        : "r"(a[0]), "r"(a[1]), "r"(a[2]), "r"(a[3]), "r"(b0), "r"(b1));
}
__device__ __forceinline__ float sigf(float x) {
    return 1.0f / (1.0f + __expf(-x));
}
// load 4 consecutive halves -> float4
__device__ __forceinline__ float4 ldh4(const __half* p) {
    uint2 v = *(const uint2*)p;
    float2 f0 = __half22float2(*(__half2*)&v.x);
    float2 f1 = __half22float2(*(__half2*)&v.y);
    return make_float4(f0.x, f0.y, f1.x, f1.y);
}

// ---------------------------------------------------------------------------
// fp16 GEMM: C[1024,2048] = A[1024,512] @ Bt^T (+bias), f32 accum.
// mode 0: step GEMM -> g_G (fp16); mode 1: act-split -> ipre16/o/u/fx16
// (byte-identical engine to the 137.7us reproduced baseline)
// ---------------------------------------------------------------------------
__global__ __launch_bounds__(512, 1)
void gemm_mma(const __half* __restrict__ A, const __half* __restrict__ Bt,
              const float* __restrict__ bias, int mode) {
    extern __shared__ __half smh[];
    const uint32_t smbase = smem_u32(smh);

    const int tid  = threadIdx.x;
    const int wid  = tid >> 5, lane = tid & 31;
    const int lq   = lane >> 2, cq = lane & 3;
    const int mw   = wid >> 2, nw = wid & 3;          // 4x4 warp grid
    const int bm   = blockIdx.y * 128, bn = blockIdx.x * 128;

    const int rowin = lane & 7;
    const int jA    = lane >> 3;
    const int jAlo  = (jA & 1) << 3;
    const int jAhi  = jA >> 1;

    int abyte[2], asw[2];
#pragma unroll
    for (int mt = 0; mt < 2; mt++) {
        int r = mw * 32 + mt * 16 + jAlo + rowin;
        abyte[mt] = r * 128; asw[mt] = r & 7;
    }
    int bbyte[4], bsw[4];
#pragma unroll
    for (int nt = 0; nt < 4; nt++) {
        int r = nw * 32 + nt * 8 + rowin;
        bbyte[nt] = r * 128; bsw[nt] = r & 7;
    }

    auto issue = [&](int s, int buf) {
        __half* da = smh + buf * A_SLH;
        __half* db = smh + (2 + buf) * A_SLH;
#pragma unroll
        for (int i = 0; i < 2; i++) {
            int idx = tid + (i << 9);
            int row = idx >> 3, c4 = idx & 7;
            cp16(smem_u32(da + row * KC + ((c4 ^ (row & 7)) << 3)),
                 A + (size_t)(bm + row) * NH + s * KC + (c4 << 3));
            cp16(smem_u32(db + row * KC + ((c4 ^ (row & 7)) << 3)),
                 Bt + (size_t)(bn + row) * NH + s * KC + (c4 << 3));
        }
        cp_commit();
    };

    float acc[2][4][4];
#pragma unroll
    for (int mt = 0; mt < 2; mt++)
#pragma unroll
        for (int nt = 0; nt < 4; nt++)
#pragma unroll
            for (int q = 0; q < 4; q++) acc[mt][nt][q] = 0.f;

    issue(0, 0);

    for (int s = 0; s < NCH; s++) {
        const int buf = s & 1;
        cp_wait<0>();
        __syncthreads();
        if (s + 1 < NCH) issue(s + 1, buf ^ 1);

        const uint32_t aB = smbase + (uint32_t)buf * (A_SLH * 2);
        const uint32_t bB = smbase + (uint32_t)(2 + buf) * (A_SLH * 2);
#pragma unroll
        for (int p = 0; p < 2; p++) {
            uint32_t br[4][4];
#pragma unroll
            for (int nt = 0; nt < 4; nt++)
                ldsm4(br[nt][0], br[nt][1], br[nt][2], br[nt][3],
                      bB + bbyte[nt] + ((((p << 2) + jA) ^ bsw[nt]) << 4));
            uint32_t ar[2][2][4];
#pragma unroll
            for (int kkl = 0; kkl < 2; kkl++)
#pragma unroll
                for (int mt = 0; mt < 2; mt++)
                    ldsm4(ar[kkl][mt][0], ar[kkl][mt][1],
                          ar[kkl][mt][2], ar[kkl][mt][3],
                          aB + abyte[mt] +
                          ((((p << 2) + (kkl << 1) + jAhi) ^ asw[mt]) << 4));
#pragma unroll
            for (int kkl = 0; kkl < 2; kkl++)
#pragma unroll
                for (int nt = 0; nt < 4; nt++)
#pragma unroll
                    for (int mt = 0; mt < 2; mt++)
                        mma16816(acc[mt][nt], ar[kkl][mt],
                                 br[nt][kkl << 1], br[nt][(kkl << 1) + 1]);
        }
    }

    if (mode == 0) {
#pragma unroll
        for (int mt = 0; mt < 2; mt++) {
            int row0 = bm + mw * 32 + mt * 16 + lq;
#pragma unroll
            for (int nt = 0; nt < 4; nt++) {
                int col = bn + nw * 32 + nt * 8 + (cq << 1);
                float bx = bias[col], by = bias[col + 1];
                *(__half2*)(g_G + (size_t)row0 * NW + col) =
                    __floats2half2_rn(acc[mt][nt][0] + bx, acc[mt][nt][1] + by);
                *(__half2*)(g_G + (size_t)(row0 + 8) * NW + col) =
                    __floats2half2_rn(acc[mt][nt][2] + bx, acc[mt][nt][3] + by);
            }
        }
    } else {
        const int seg = bn >> 9;
#pragma unroll
        for (int mt = 0; mt < 2; mt++) {
            int row0 = bm + mw * 32 + mt * 16 + lq;
#pragma unroll
            for (int nt = 0; nt < 4; nt++) {
                int lcol = (bn & 511) + nw * 32 + nt * 8 + (cq << 1);
                float v[4] = { acc[mt][nt][0], acc[mt][nt][1],
                               acc[mt][nt][2], acc[mt][nt][3] };
                if (seg == 0) {
                    *(__half2*)(g_ipre + (size_t)row0 * NH + lcol) =
                        __floats2half2_rn(v[0], v[1]);
                    *(__half2*)(g_ipre + (size_t)(row0 + 8) * NH + lcol) =
                        __floats2half2_rn(v[2], v[3]);
                } else if (seg == 1) {
                    *(float2*)(g_o + (size_t)row0 * NH + lcol) =
                        make_float2(sigf(v[0]), sigf(v[1]));
                    *(float2*)(g_o + (size_t)(row0 + 8) * NH + lcol) =
                        make_float2(sigf(v[2]), sigf(v[3]));
                } else if (seg == 2) {
                    *(float2*)(g_u + (size_t)row0 * NH + lcol) =
                        make_float2(tanhf(v[0]), tanhf(v[1]));
                    *(float2*)(g_u + (size_t)(row0 + 8) * NH + lcol) =
                        make_float2(tanhf(v[2]), tanhf(v[3]));
                } else {
                    *(__half2*)(g_fx + (size_t)row0 * NH + lcol) =
                        __floats2half2_rn(v[0], v[1]);
                    *(__half2*)(g_fx + (size_t)(row0 + 8) * NH + lcol) =
                        __floats2half2_rn(v[2], v[3]);
                }
            }
        }
    }
}

// ---------------------------------------------------------------------------
// Fused per-step phase: 4 rows per 512-thread block (grid = 256).
// Per-row math identical to the 137.7us baseline (bit-identical results).
// ---------------------------------------------------------------------------
__global__ __launch_bounds__(512)
void phase_k(int step, int step0, int cur, float* __restrict__ out) {
    const int r = blockIdx.x * 4 + (threadIdx.x >> 7);
    const int t = threadIdx.x & 127;
    const int b = r >> 7, n = r & 127;
    const int browbase = b * NSQ;
    const int sb = step * 8 + b;
    const float* c_cur = g_c[cur];
    float* c_nxt = g_c[cur ^ 1];

    float4 acc = make_float4(0.f, 0.f, 0.f, 0.f);
    const int cnt = g_cntIU[sb * 128 + n];
    if (step0) {
        int nr = g_cntR[sb * 128 + n];
        int nl = cnt - nr;
        float4 bAr = ((const float4*)g_bstep)[t];
        float4 bAl = ((const float4*)g_bstep)[128 + t];
        float fr = (float)nr, fl = (float)nl;
        acc.x = fr * bAr.x + fl * bAl.x;
        acc.y = fr * bAr.y + fl * bAl.y;
        acc.z = fr * bAr.z + fl * bAl.z;
        acc.w = fr * bAr.w + fl * bAl.w;
    } else {
        const int* lst = g_listIU + ((size_t)sb * 128 + n) * 256;
        for (int k = 0; k < cnt; k++) {
            int e = lst[k];
            int sp = e & 255, seg = e >> 8;
            float4 v = ldh4(g_G + (size_t)(browbase + sp) * NW +
                            seg * 512 + t * 4);
            acc.x += v.x; acc.y += v.y; acc.z += v.z; acc.w += v.w;
        }
    }

    float4 ip = ldh4(g_ipre + (size_t)r * NH + t * 4);
    float4 uv = ((const float4*)g_u)[(size_t)r * 128 + t];
    float4 cf;
    cf.x = sigf(ip.x + acc.x) * uv.x;
    cf.y = sigf(ip.y + acc.y) * uv.y;
    cf.z = sigf(ip.z + acc.z) * uv.z;
    cf.w = sigf(ip.w + acc.w) * uv.w;

    if (!step0) {
        const int cd = g_cntD[sb * 128 + n];
        if (cd) {
            const int* ld = g_listD + ((size_t)sb * 128 + n) * 128;
            float4 fx4 = ldh4(g_fx + (size_t)r * NH + t * 4);
            for (int k = 0; k < cd; k++) {
                int e = ld[k];
                int sp = e & 255;
                int rr = (e >> 16) & 255, ll = (e >> 24) & 255;
                float4 fr4 = ldh4(g_G + (size_t)(browbase + rr) * NW +
                                  1024 + t * 4);
                float4 fl4 = ldh4(g_G + (size_t)(browbase + ll) * NW +
                                  1536 + t * 4);
                float4 cv  = ((const float4*)c_cur)[(size_t)(browbase + sp) * 128 + t];
                cf.x += sigf(fx4.x + fr4.x + fl4.x) * cv.x;
                cf.y += sigf(fx4.y + fr4.y + fl4.y) * cv.y;
                cf.z += sigf(fx4.z + fr4.z + fl4.z) * cv.z;
                cf.w += sigf(fx4.w + fr4.w + fl4.w) * cv.w;
            }
        }
    }

    float4 ov = ((const float4*)g_o)[(size_t)r * 128 + t];
    float4 hf;
    hf.x = ov.x * tanhf(cf.x);
    hf.y = ov.y * tanhf(cf.y);
    hf.z = ov.z * tanhf(cf.z);
    hf.w = ov.w * tanhf(cf.w);

    const int nm = g_nmask[step];
    if (r < nm) {
        const int q = g_dest[step * ROWS + r];
        if (out) {
            ((float4*)out)[(size_t)q * 128 + t] = hf;
        } else {
            ((float4*)g_h)[(size_t)q * 128 + t] = hf;
            ((float4*)c_nxt)[(size_t)q * 128 + t] = cf;
            __half2* hrw = (__half2*)(g_hr + (size_t)q * NH + t * 4);
            hrw[0] = __floats2half2_rn(hf.x, hf.y);
            hrw[1] = __floats2half2_rn(hf.z, hf.w);
        }
    }
    if (!g_maskv[step * ROWS + r]) {
        if (out) {
            ((float4*)out)[(size_t)r * 128 + t] =
                ((const float4*)g_h)[(size_t)r * 128 + t];
        } else {
            ((float4*)c_nxt)[(size_t)r * 128 + t] =
                ((const float4*)c_cur)[(size_t)r * 128 + t];
        }
    }
}

// ---------------------------------------------------------------------------
// Single merged prep kernel (byte-identical to reproduced baseline)
// ---------------------------------------------------------------------------
__global__ __launch_bounds__(256)
void prep_k(const int* __restrict__ ids, const float* __restrict__ emb,
            const int* __restrict__ tree,
            const float* __restrict__ Wioux, const float* __restrict__ Wfx,
            const float* __restrict__ Wr, const float* __restrict__ Wl,
            const float* __restrict__ f0, const float* __restrict__ f1,
            const float* __restrict__ f2, const float* __restrict__ f3,
            const float* __restrict__ br, const float* __restrict__ bl,
            const float* __restrict__ bf0, const float* __restrict__ bf1,
            const float* __restrict__ bf2, const float* __restrict__ bf3) {
    const int blk = blockIdx.x;
    const int t = threadIdx.x;

    if (blk < 2048) {                       // ---- transposes ----
        __shared__ float tile[32][33];
        int y = blk >> 4;
        const float *s1, *s2 = nullptr;
        __half* dst; int n_off, ld1, ny;
        if (y < 48)       { dst = g_Wt_pre;  n_off = 0;    s1 = Wioux; ld1 = 1536; ny = y; }
        else if (y < 64)  { dst = g_Wt_pre;  n_off = 1536; s1 = Wfx;   ld1 = 512;  ny = y - 48; }
        else if (y < 80)  { dst = g_Wt_step; n_off = 0;    s1 = Wr;    ld1 = 1536; ny = y - 64; }
        else if (y < 96)  { dst = g_Wt_step; n_off = 512;  s1 = Wl;    ld1 = 1536; ny = y - 80; }
        else if (y < 112) { dst = g_Wt_step; n_off = 1024; s1 = f0; s2 = f1; ld1 = 512; ny = y - 96; }
        else              { dst = g_Wt_step; n_off = 1536; s1 = f2; s2 = f3; ld1 = 512; ny = y - 112; }

        int k0 = (blk & 15) * 32, n0 = ny * 32;
        int tx = t & 31, ty = t >> 5;
        for (int i = ty; i < 32; i += 8) {
            float v = s1[(size_t)(k0 + i) * ld1 + n0 + tx];
            if (s2) v += s2[(size_t)(k0 + i) * NH + n0 + tx];
            tile[i][tx] = v;
        }
        __syncthreads();
        for (int i = ty; i < 32; i += 8) {
            dst[(size_t)(n_off + n0 + i) * NH + k0 + tx] =
                __float2half(tile[tx][i]);
        }
    } else if (blk < 2560) {                // ---- init ----
        int row = (blk - 2048) * 2 + (t >> 7);
        int tt = t & 127;
        int tok = ids[row];
        float4 v = ((const float4*)emb)[(size_t)tok * 128 + tt];
        __half2* xw = (__half2*)(g_x + (size_t)row * NH + tt * 4);
        xw[0] = __floats2half2_rn(v.x, v.y);
        xw[1] = __floats2half2_rn(v.z, v.w);
        float4 z = make_float4(0.f, 0.f, 0.f, 0.f);
        ((float4*)g_h)[(size_t)row * 128 + tt]      = z;
        ((float4*)(g_c[0]))[(size_t)row * 128 + tt] = z;
        __half2 zh = __floats2half2_rn(0.f, 0.f);
        __half2* hrw = (__half2*)(g_hr + (size_t)row * NH + tt * 4);
        hrw[0] = zh; hrw[1] = zh;
        if (row < 4) {
            int j = tt * 4;
            const float* s1 = (row == 0) ? br : (row == 1) ? bl
                            : (row == 2) ? bf0 : bf2;
            const float* s2 = (row == 2) ? bf1 : (row == 3) ? bf3 : nullptr;
            float4 bv = *(const float4*)(s1 + j);
            if (s2) {
                float4 b2v = *(const float4*)(s2 + j);
                bv.x += b2v.x; bv.y += b2v.y; bv.z += b2v.z; bv.w += b2v.w;
            }
            *(float4*)(g_bstep + row * 512 + j) = bv;
        }
    } else if (blk < 2624) {                // ---- lists ----
        __shared__ int s_id[NSQ], s_ir[NSQ], s_il[NSQ];
        int sb = blk - 2560;
        int s = sb >> 3, b = sb & 7;
        int base = (b * NSTEPS + s) * 3;
        if (t < 128) {
            s_id[t] = tree[(base + 0) * NSQ + t];
            s_ir[t] = tree[(base + 1) * NSQ + t];
            s_il[t] = tree[(base + 2) * NSQ + t];
        }
        __syncthreads();
        if (t < 128) {
            int n = t;
            int* lIU = g_listIU + ((size_t)sb * 128 + n) * 256;
            int c = 0;
            for (int sp = 0; sp < NSQ; sp++) if (s_ir[sp] == n) lIU[c++] = sp;
            int cr = c;
            for (int sp = 0; sp < NSQ; sp++) if (s_il[sp] == n) lIU[c++] = sp | 256;
            g_cntIU[sb * 128 + n] = c;
            g_cntR[sb * 128 + n] = cr;
            int* lD = g_listD + ((size_t)sb * 128 + n) * 128;
            int cd = 0;
            for (int sp = 0; sp < NSQ; sp++)
                if (s_id[sp] == n)
                    lD[cd++] = sp | (s_ir[sp] << 16) | (s_il[sp] << 24);
            g_cntD[sb * 128 + n] = cd;
        }
    } else {                                // ---- ranks ----
        __shared__ int wsum[8];
        int s = blk - 2624;
        int lane = t & 31, w = t >> 5;
        int m[4], loc[4];
        int sum = 0;
#pragma unroll
        for (int q = 0; q < 4; q++) {
            int p = t * 4 + q;
            int b = p >> 7, ss = p & 127;
            int idxd = tree[((b * NSTEPS + s) * 3) * NSQ + ss];
            m[q] = (idxd != 0) ? 1 : 0;
            g_maskv[s * ROWS + p] = m[q];
            loc[q] = sum;
            sum += m[q];
        }
        int e = sum;
#pragma unroll
        for (int off = 1; off < 32; off <<= 1) {
            int o = __shfl_up_sync(0xFFFFFFFFu, e, off);
            if (lane >= off) e += o;
        }
        if (lane == 31) wsum[w] = e;
        __syncthreads();
        if (t == 0) {
            int a = 0;
#pragma unroll
            for (int i = 0; i < 8; i++) { int v = wsum[i]; wsum[i] = a; a += v; }
            g_nmask[s] = a;
        }
        __syncthreads();
        int pre = wsum[w] + e - sum;
#pragma unroll
        for (int q = 0; q < 4; q++)
            if (m[q]) g_dest[s * ROWS + pre + loc[q]] = t * 4 + q;
    }
}

// ---------------------------------------------------------------------------
// Launch
// ---------------------------------------------------------------------------
extern "C" void kernel_launch(void* const* d_in, const int* in_sizes, int n_in,
                              void* d_out, int out_size) {
    const int*   ids      = (const int*)d_in[0];
    const int*   tree     = (const int*)d_in[1];
    const float* emb      = (const float*)d_in[2];
    const float* W_ioux   = (const float*)d_in[3];
    const float* W_iouh_r = (const float*)d_in[4];
    const float* b_iouh_r = (const float*)d_in[5];
    const float* W_iouh_l = (const float*)d_in[6];
    const float* b_iouh_l = (const float*)d_in[7];
    const float* W_fx     = (const float*)d_in[8];
    const float* W_fh0    = (const float*)d_in[9];
    const float* b_fh0    = (const float*)d_in[10];
    const float* W_fh1    = (const float*)d_in[11];
    const float* b_fh1    = (const float*)d_in[12];
    const float* W_fh2    = (const float*)d_in[13];
    const float* b_fh2    = (const float*)d_in[14];
    const float* W_fh3    = (const float*)d_in[15];
    const float* b_fh3    = (const float*)d_in[16];

    cudaFuncSetAttribute(gemm_mma, cudaFuncAttributeMaxDynamicSharedMemorySize,
                         SMEM_DYN);

    __half *pX, *pWtPre, *pWtStep, *pHr;
    float *pB;
    cudaGetSymbolAddress((void**)&pX,      g_x);
    cudaGetSymbolAddress((void**)&pWtPre,  g_Wt_pre);
    cudaGetSymbolAddress((void**)&pWtStep, g_Wt_step);
    cudaGetSymbolAddress((void**)&pB,      g_bstep);
    cudaGetSymbolAddress((void**)&pHr,     g_hr);

    prep_k<<<2632, 256>>>(ids, emb, tree, W_ioux, W_fx,
                          W_iouh_r, W_iouh_l, W_fh0, W_fh1, W_fh2, W_fh3,
                          b_iouh_r, b_iouh_l, b_fh0, b_fh1, b_fh2, b_fh3);

    // precompute GEMM with fused activation-split epilogue
    gemm_mma<<<dim3(NW / 128, ROWS / 128), 512, SMEM_DYN>>>(pX, pWtPre,
                                                            nullptr, 1);

    // step 0: h=0 (i-gate from bias counts), c=0 (no fc)
    phase_k<<<ROWS / 4, 512>>>(0, 1, 0, nullptr);

    int cur = 1;
    for (int s = 1; s < NSTEPS; s++) {
        gemm_mma<<<dim3(NW / 128, ROWS / 128), 512, SMEM_DYN>>>(
            pHr, pWtStep, pB, 0);
        phase_k<<<ROWS / 4, 512>>>(s, 0, cur,
                                   (s == NSTEPS - 1) ? (float*)d_out : nullptr);
        cur ^= 1;
    }
}